// round 3
// baseline (speedup 1.0000x reference)
#include <cuda_runtime.h>

#define SEQ   8192
#define HD    1024
#define G4    4096
#define NIN   64
#define NLAYER 5
#define NCTA  128

// ---------------- scratch (device globals; no allocation allowed) ------------
__device__ float              g_bufA[(size_t)SEQ * HD];   // 32 MB activation ping
__device__ float              g_bufB[(size_t)SEQ * HD];   // 32 MB activation pong
__device__ float              g_Z[(size_t)SEQ * G4];      // 128 MB input-projection buffer
__device__ unsigned long long g_hp[2][HD];                // tagged hidden state {f32 h, u32 tag}

// ---------------- math helpers ----------------------------------------------
__device__ __forceinline__ float sigmf(float x) { return 1.0f / (1.0f + __expf(-x)); }
__device__ __forceinline__ float tanh_fast(float x) { return 1.0f - 2.0f / (__expf(2.0f * x) + 1.0f); }

__device__ __forceinline__ unsigned long long ld_rlx64(const unsigned long long* p) {
    unsigned long long v;
    asm volatile("ld.relaxed.gpu.global.b64 %0, [%1];" : "=l"(v) : "l"(p) : "memory");
    return v;
}
__device__ __forceinline__ void st_rlx64(unsigned long long* p, unsigned long long v) {
    asm volatile("st.relaxed.gpu.global.b64 [%0], %1;" :: "l"(p), "l"(v) : "memory");
}
__device__ __forceinline__ unsigned long long pack_ht(float h, unsigned tag) {
    unsigned long long v;
    asm("mov.b64 %0, {%1, %2};" : "=l"(v) : "f"(h), "r"(tag));   // lo = h, hi = tag
    return v;
}

// ---------------- init: clear tags (replay safety across graph runs) ---------
__global__ void k_init() {
    const int i = threadIdx.x + blockIdx.x * blockDim.x;   // 0..2047
    ((unsigned long long*)g_hp)[i] = 0ull;                 // tag 0 < any want (wants start at 1)
}

// ---------------- first layer: leaky_relu(x @ w1^T + b1) ---------------------
__global__ __launch_bounds__(256) void k_first(const float* __restrict__ x,
                                               const float* __restrict__ w1,
                                               const float* __restrict__ b1,
                                               float* __restrict__ out) {
    __shared__ float xs[64][NIN];
    __shared__ float ws[64][NIN + 1];
    const int t0 = blockIdx.x * 64;
    const int h0 = blockIdx.y * 64;
    const int tid = threadIdx.x;

    for (int i = tid; i < 64 * NIN; i += 256)
        xs[i >> 6][i & 63] = x[(size_t)(t0 + (i >> 6)) * NIN + (i & 63)];
    for (int i = tid; i < 64 * NIN; i += 256)
        ws[i >> 6][i & 63] = w1[(size_t)(h0 + (i >> 6)) * NIN + (i & 63)];
    __syncthreads();

    const int h = tid & 63, tq = tid >> 6;
    float acc[16];
#pragma unroll
    for (int i = 0; i < 16; i++) acc[i] = 0.0f;

#pragma unroll 16
    for (int k = 0; k < NIN; k++) {
        const float wv = ws[h][k];
#pragma unroll
        for (int i = 0; i < 16; i++) acc[i] = fmaf(xs[tq * 16 + i][k], wv, acc[i]);
    }
    const float bb = b1[h0 + h];
#pragma unroll
    for (int i = 0; i < 16; i++) {
        float v = acc[i] + bb;
        v = (v >= 0.0f) ? v : 0.01f * v;
        out[(size_t)(t0 + tq * 16 + i) * HD + h0 + h] = v;
    }
}

// ---------------- input-projection GEMM: Z = X @ Wih^T + (b_ih + b_hh) -------
__global__ __launch_bounds__(256, 2) void k_gemm(const float* __restrict__ A,   // (SEQ, HD)
                                                 const float* __restrict__ W,   // (G4, HD)
                                                 const float* __restrict__ bi,
                                                 const float* __restrict__ bh) {
    __shared__ float As[8][128];
    __shared__ float Bs[8][128];
    const int tid = threadIdx.x;
    const int tx = tid & 15, ty = tid >> 4;
    const int m0 = blockIdx.y * 128, n0 = blockIdx.x * 128;
    const int lr = tid >> 1, lk = (tid & 1) * 4;

    const float* Ap = A + (size_t)(m0 + lr) * HD + lk;
    const float* Wp = W + (size_t)(n0 + lr) * HD + lk;

    float acc[8][8];
#pragma unroll
    for (int i = 0; i < 8; i++)
#pragma unroll
        for (int j = 0; j < 8; j++) acc[i][j] = 0.0f;

    float4 av = *(const float4*)(Ap);
    float4 bv = *(const float4*)(Wp);

    for (int k0 = 0; k0 < HD; k0 += 8) {
        __syncthreads();
        As[lk + 0][lr] = av.x; As[lk + 1][lr] = av.y; As[lk + 2][lr] = av.z; As[lk + 3][lr] = av.w;
        Bs[lk + 0][lr] = bv.x; Bs[lk + 1][lr] = bv.y; Bs[lk + 2][lr] = bv.z; Bs[lk + 3][lr] = bv.w;
        __syncthreads();
        if (k0 + 8 < HD) {
            av = *(const float4*)(Ap + k0 + 8);
            bv = *(const float4*)(Wp + k0 + 8);
        }
#pragma unroll
        for (int kk = 0; kk < 8; kk++) {
            float ar[8], br[8];
            *(float4*)(ar)     = *(const float4*)&As[kk][ty * 8];
            *(float4*)(ar + 4) = *(const float4*)&As[kk][ty * 8 + 4];
            *(float4*)(br)     = *(const float4*)&Bs[kk][tx * 8];
            *(float4*)(br + 4) = *(const float4*)&Bs[kk][tx * 8 + 4];
#pragma unroll
            for (int i = 0; i < 8; i++)
#pragma unroll
                for (int j = 0; j < 8; j++) acc[i][j] = fmaf(ar[i], br[j], acc[i][j]);
        }
    }
    float bb[8];
#pragma unroll
    for (int j = 0; j < 8; j++) bb[j] = bi[n0 + tx * 8 + j] + bh[n0 + tx * 8 + j];
#pragma unroll
    for (int i = 0; i < 8; i++) {
        const size_t m = (size_t)(m0 + ty * 8 + i);
        float4 o0, o1;
        o0.x = acc[i][0] + bb[0]; o0.y = acc[i][1] + bb[1];
        o0.z = acc[i][2] + bb[2]; o0.w = acc[i][3] + bb[3];
        o1.x = acc[i][4] + bb[4]; o1.y = acc[i][5] + bb[5];
        o1.z = acc[i][6] + bb[6]; o1.w = acc[i][7] + bb[7];
        *(float4*)&g_Z[m * G4 + n0 + tx * 8]     = o0;
        *(float4*)&g_Z[m * G4 + n0 + tx * 8 + 4] = o1;
    }
}

// ---------------- prep: seed h_{-1} = h0[layer] into buffer 1, tag = base ----
__global__ void k_prep(const float* __restrict__ h0l, unsigned base) {
    const int i = threadIdx.x + blockIdx.x * blockDim.x;
    if (i < HD) g_hp[1][i] = pack_ht(h0l[i], base);
}

// ---------------- recurrent persistent kernel --------------------------------
// 128 CTAs x 256 threads. CTA b owns units [8b, 8b+8); warp w -> unit u = 8b+w,
// gate rows {u, 1024+u, 2048+u, 3072+u}. Weights in registers as f32x2 pairs.
// Sync: h published as {h, tag} in one 64-bit relaxed store; consumers poll the
// tagged word directly (single L2 round trip, no fence, no separate flag).
__global__ __launch_bounds__(256, 1) void k_rec(const float* __restrict__ Whh,  // (G4, HD)
                                                const float* __restrict__ c0l,  // (HD)
                                                float* __restrict__ Xout,       // (SEQ, HD)
                                                unsigned base) {
    __shared__ float sh[2][HD];                 // double-buffered staged h
    const int tid = threadIdx.x;
    const int w = tid >> 5, lane = tid & 31;
    const int u = blockIdx.x * 8 + w;

    unsigned sb;
    asm("{ .reg .u64 t; cvta.to.shared.u64 t, %1; cvt.u32.u64 %0, t; }"
        : "=r"(sb) : "l"((void*)sh));
    sb += (unsigned)lane * 8u;

    // packed weight pairs: lane owns k in {64j+2*lane, 64j+2*lane+1}
    unsigned long long wp[4][16];
#pragma unroll
    for (int g = 0; g < 4; g++) {
        const float* rp = Whh + (size_t)(g * HD + u) * HD + 2 * lane;
#pragma unroll
        for (int j = 0; j < 16; j++) {
            const float2 v = *(const float2*)(rp + 64 * j);
            asm("mov.b64 %0, {%1, %2};" : "=l"(wp[g][j]) : "f"(v.x), "f"(v.y));
        }
    }
    float c = c0l[u];   // only lane 0's copy is used

#pragma unroll 1
    for (int t = 0; t < SEQ; t++) {
        // prefetch this step's input projection (independent of h)
        float z0 = 0.f, z1 = 0.f, z2 = 0.f, z3 = 0.f;
        if (lane == 0) {
            const float* zp = g_Z + (size_t)t * G4 + u;
            z0 = zp[0]; z1 = zp[HD]; z2 = zp[2 * HD]; z3 = zp[3 * HD];
        }

        // poll this thread's 4 tagged words; data+validity in one access
        const unsigned want = base + (unsigned)t;
        {
            const unsigned long long* p = &g_hp[(t + 1) & 1][tid * 4];
            unsigned long long v0, v1, v2, v3;
            for (;;) {
                v0 = ld_rlx64(p + 0); v1 = ld_rlx64(p + 1);
                v2 = ld_rlx64(p + 2); v3 = ld_rlx64(p + 3);
                const unsigned d = ((unsigned)(v0 >> 32) ^ want) | ((unsigned)(v1 >> 32) ^ want)
                                 | ((unsigned)(v2 >> 32) ^ want) | ((unsigned)(v3 >> 32) ^ want);
                if (d == 0u) break;
            }
            float4 hv;
            hv.x = __uint_as_float((unsigned)v0);
            hv.y = __uint_as_float((unsigned)v1);
            hv.z = __uint_as_float((unsigned)v2);
            hv.w = __uint_as_float((unsigned)v3);
            *(float4*)&sh[t & 1][tid * 4] = hv;
        }
        __syncthreads();

        // packed dot: 64 x fma.rn.f32x2 + 16 x LDS.64
        const unsigned sbase = sb + (unsigned)((t & 1) << 12);
        unsigned long long a0 = 0ull, a1 = 0ull, a2 = 0ull, a3 = 0ull;
#pragma unroll
        for (int j = 0; j < 16; j++) {
            unsigned long long hp;
            asm volatile("ld.shared.b64 %0, [%1];" : "=l"(hp) : "r"(sbase + (unsigned)(j * 256)));
            asm("fma.rn.f32x2 %0, %1, %2, %0;" : "+l"(a0) : "l"(wp[0][j]), "l"(hp));
            asm("fma.rn.f32x2 %0, %1, %2, %0;" : "+l"(a1) : "l"(wp[1][j]), "l"(hp));
            asm("fma.rn.f32x2 %0, %1, %2, %0;" : "+l"(a2) : "l"(wp[2][j]), "l"(hp));
            asm("fma.rn.f32x2 %0, %1, %2, %0;" : "+l"(a3) : "l"(wp[3][j]), "l"(hp));
        }
        float s0, s1, s2, s3;
        {
            float x, y;
            asm("mov.b64 {%0,%1}, %2;" : "=f"(x), "=f"(y) : "l"(a0)); s0 = x + y;
            asm("mov.b64 {%0,%1}, %2;" : "=f"(x), "=f"(y) : "l"(a1)); s1 = x + y;
            asm("mov.b64 {%0,%1}, %2;" : "=f"(x), "=f"(y) : "l"(a2)); s2 = x + y;
            asm("mov.b64 {%0,%1}, %2;" : "=f"(x), "=f"(y) : "l"(a3)); s3 = x + y;
        }
#pragma unroll
        for (int off = 16; off; off >>= 1) {
            s0 += __shfl_xor_sync(0xffffffffu, s0, off);
            s1 += __shfl_xor_sync(0xffffffffu, s1, off);
            s2 += __shfl_xor_sync(0xffffffffu, s2, off);
            s3 += __shfl_xor_sync(0xffffffffu, s3, off);
        }
        if (lane == 0) {
            const float ig = sigmf(s0 + z0);
            const float fg = sigmf(s1 + z1);
            const float gg = tanh_fast(s2 + z2);
            const float og = sigmf(s3 + z3);
            c = fg * c + ig * gg;
            const float h = og * tanh_fast(c);
            st_rlx64(&g_hp[t & 1][u], pack_ht(h, want + 1u));   // publish: data+tag, one word
            Xout[(size_t)t * HD + u] = h;                        // off the critical path
        }
        // no trailing barrier: next iteration's STS targets the other sh buffer,
        // and the single barrier above orders buffer reuse two steps apart.
    }
}

// ---------------- final: tanh(leaky_relu(X) @ w2^T + b2) ---------------------
__global__ __launch_bounds__(256) void k_final(const float* __restrict__ Xin,
                                               const float* __restrict__ w2,   // (NIN, HD)
                                               const float* __restrict__ b2,
                                               float* __restrict__ y) {
    __shared__ float xs[64][65];
    __shared__ float ws[64][65];
    const int t0 = blockIdx.x * 64;
    const int tid = threadIdx.x;
    const int o = tid & 63, tq = tid >> 6;

    float acc[16];
#pragma unroll
    for (int i = 0; i < 16; i++) acc[i] = 0.0f;

    for (int k0 = 0; k0 < HD; k0 += 64) {
        __syncthreads();
        for (int i = tid; i < 64 * 64; i += 256) {
            const int r = i >> 6, cc = i & 63;
            float v = Xin[(size_t)(t0 + r) * HD + k0 + cc];
            xs[r][cc] = (v >= 0.0f) ? v : 0.01f * v;
            ws[r][cc] = w2[(size_t)r * HD + k0 + cc];
        }
        __syncthreads();
#pragma unroll 16
        for (int k = 0; k < 64; k++) {
            const float wv = ws[o][k];
#pragma unroll
            for (int i = 0; i < 16; i++) acc[i] = fmaf(xs[tq * 16 + i][k], wv, acc[i]);
        }
    }
    const float bb = b2[o];
#pragma unroll
    for (int i = 0; i < 16; i++)
        y[(size_t)(t0 + tq * 16 + i) * NIN + o] = tanh_fast(acc[i] + bb);
}

// ---------------- host launcher ----------------------------------------------
extern "C" void kernel_launch(void* const* d_in, const int* in_sizes, int n_in,
                              void* d_out, int out_size) {
    const float* data_in = (const float*)d_in[0];
    const float* w1      = (const float*)d_in[1];
    const float* b1      = (const float*)d_in[2];
    const float* W_ih    = (const float*)d_in[3];
    const float* W_hh    = (const float*)d_in[4];
    const float* b_ih    = (const float*)d_in[5];
    const float* b_hh    = (const float*)d_in[6];
    const float* w2      = (const float*)d_in[7];
    const float* b2      = (const float*)d_in[8];
    const float* h0      = (const float*)d_in[9];
    const float* c0      = (const float*)d_in[10];
    float* out = (float*)d_out;

    static float* dA = nullptr;
    static float* dB = nullptr;
    if (!dA) {   // host-side symbol query, not an allocation
        cudaGetSymbolAddress((void**)&dA, g_bufA);
        cudaGetSymbolAddress((void**)&dB, g_bufB);
    }
    float* bufs[2] = { dA, dB };

    k_init<<<8, 256>>>();   // zero tags -> graph-replay safe
    k_first<<<dim3(SEQ / 64, HD / 64), 256>>>(data_in, w1, b1, dA);

    for (int l = 0; l < NLAYER; l++) {
        const float* Xin = bufs[l & 1];
        float* Xout = bufs[(l & 1) ^ 1];
        const unsigned base = (unsigned)(l * (SEQ + 2) + 1);   // disjoint, >0 tag ranges
        k_gemm<<<dim3(G4 / 128, SEQ / 128), 256>>>(Xin,
                                                   W_ih + (size_t)l * G4 * HD,
                                                   b_ih + (size_t)l * G4,
                                                   b_hh + (size_t)l * G4);
        k_prep<<<4, 256>>>(h0 + (size_t)l * HD, base);
        k_rec<<<NCTA, 256>>>(W_hh + (size_t)l * G4 * HD,
                             c0 + (size_t)l * HD,
                             Xout,
                             base);
    }
    k_final<<<SEQ / 64, 256>>>(bufs[NLAYER & 1], w2, b2, out);
}

// round 4
// speedup vs baseline: 1.0790x; 1.0790x over previous
#include <cuda_runtime.h>

#define SEQ   8192
#define HD    1024
#define G4    4096
#define NIN   64
#define NLAYER 5
#define NCTA  128

// ---------------- scratch (device globals; no allocation allowed) ------------
__device__ float              g_bufA[(size_t)SEQ * HD];   // 32 MB activation ping
__device__ float              g_bufB[(size_t)SEQ * HD];   // 32 MB activation pong
__device__ float              g_Z[(size_t)SEQ * G4];      // 128 MB input-projection buffer
__device__ unsigned long long g_hp[2][HD];                // tagged hidden state {f32 h, u32 tag}

// ---------------- math helpers ----------------------------------------------
__device__ __forceinline__ float sigmf(float x) { return 1.0f / (1.0f + __expf(-x)); }
__device__ __forceinline__ float tanh_fast(float x) { return 1.0f - 2.0f / (__expf(2.0f * x) + 1.0f); }

__device__ __forceinline__ void st_rlx64(unsigned long long* p, unsigned long long v) {
    asm volatile("st.relaxed.gpu.global.b64 [%0], %1;" :: "l"(p), "l"(v) : "memory");
}
__device__ __forceinline__ unsigned long long pack_ht(float h, unsigned tag) {
    unsigned long long v;
    asm("mov.b64 %0, {%1, %2};" : "=l"(v) : "f"(h), "r"(tag));   // lo = h, hi = tag
    return v;
}
__device__ __forceinline__ void ld_vol2(const unsigned long long* p,
                                        unsigned long long& a, unsigned long long& b) {
    asm volatile("ld.volatile.global.v2.b64 {%0, %1}, [%2];"
                 : "=l"(a), "=l"(b) : "l"(p) : "memory");
}

// ---------------- init: clear tags (replay safety across graph runs) ---------
__global__ void k_init() {
    const int i = threadIdx.x + blockIdx.x * blockDim.x;   // 0..2047
    ((unsigned long long*)g_hp)[i] = 0ull;                 // tag 0 < any want (wants start at 1)
}

// ---------------- first layer: leaky_relu(x @ w1^T + b1) ---------------------
__global__ __launch_bounds__(256) void k_first(const float* __restrict__ x,
                                               const float* __restrict__ w1,
                                               const float* __restrict__ b1,
                                               float* __restrict__ out) {
    __shared__ float xs[64][NIN];
    __shared__ float ws[64][NIN + 1];
    const int t0 = blockIdx.x * 64;
    const int h0 = blockIdx.y * 64;
    const int tid = threadIdx.x;

    for (int i = tid; i < 64 * NIN; i += 256)
        xs[i >> 6][i & 63] = x[(size_t)(t0 + (i >> 6)) * NIN + (i & 63)];
    for (int i = tid; i < 64 * NIN; i += 256)
        ws[i >> 6][i & 63] = w1[(size_t)(h0 + (i >> 6)) * NIN + (i & 63)];
    __syncthreads();

    const int h = tid & 63, tq = tid >> 6;
    float acc[16];
#pragma unroll
    for (int i = 0; i < 16; i++) acc[i] = 0.0f;

#pragma unroll 16
    for (int k = 0; k < NIN; k++) {
        const float wv = ws[h][k];
#pragma unroll
        for (int i = 0; i < 16; i++) acc[i] = fmaf(xs[tq * 16 + i][k], wv, acc[i]);
    }
    const float bb = b1[h0 + h];
#pragma unroll
    for (int i = 0; i < 16; i++) {
        float v = acc[i] + bb;
        v = (v >= 0.0f) ? v : 0.01f * v;
        out[(size_t)(t0 + tq * 16 + i) * HD + h0 + h] = v;
    }
}

// ---------------- input-projection GEMM: Z = X @ Wih^T + (b_ih + b_hh) -------
__global__ __launch_bounds__(256, 2) void k_gemm(const float* __restrict__ A,   // (SEQ, HD)
                                                 const float* __restrict__ W,   // (G4, HD)
                                                 const float* __restrict__ bi,
                                                 const float* __restrict__ bh) {
    __shared__ float As[8][128];
    __shared__ float Bs[8][128];
    const int tid = threadIdx.x;
    const int tx = tid & 15, ty = tid >> 4;
    const int m0 = blockIdx.y * 128, n0 = blockIdx.x * 128;
    const int lr = tid >> 1, lk = (tid & 1) * 4;

    const float* Ap = A + (size_t)(m0 + lr) * HD + lk;
    const float* Wp = W + (size_t)(n0 + lr) * HD + lk;

    float acc[8][8];
#pragma unroll
    for (int i = 0; i < 8; i++)
#pragma unroll
        for (int j = 0; j < 8; j++) acc[i][j] = 0.0f;

    float4 av = *(const float4*)(Ap);
    float4 bv = *(const float4*)(Wp);

    for (int k0 = 0; k0 < HD; k0 += 8) {
        __syncthreads();
        As[lk + 0][lr] = av.x; As[lk + 1][lr] = av.y; As[lk + 2][lr] = av.z; As[lk + 3][lr] = av.w;
        Bs[lk + 0][lr] = bv.x; Bs[lk + 1][lr] = bv.y; Bs[lk + 2][lr] = bv.z; Bs[lk + 3][lr] = bv.w;
        __syncthreads();
        if (k0 + 8 < HD) {
            av = *(const float4*)(Ap + k0 + 8);
            bv = *(const float4*)(Wp + k0 + 8);
        }
#pragma unroll
        for (int kk = 0; kk < 8; kk++) {
            float ar[8], br[8];
            *(float4*)(ar)     = *(const float4*)&As[kk][ty * 8];
            *(float4*)(ar + 4) = *(const float4*)&As[kk][ty * 8 + 4];
            *(float4*)(br)     = *(const float4*)&Bs[kk][tx * 8];
            *(float4*)(br + 4) = *(const float4*)&Bs[kk][tx * 8 + 4];
#pragma unroll
            for (int i = 0; i < 8; i++)
#pragma unroll
                for (int j = 0; j < 8; j++) acc[i][j] = fmaf(ar[i], br[j], acc[i][j]);
        }
    }
    float bb[8];
#pragma unroll
    for (int j = 0; j < 8; j++) bb[j] = bi[n0 + tx * 8 + j] + bh[n0 + tx * 8 + j];
#pragma unroll
    for (int i = 0; i < 8; i++) {
        const size_t m = (size_t)(m0 + ty * 8 + i);
        float4 o0, o1;
        o0.x = acc[i][0] + bb[0]; o0.y = acc[i][1] + bb[1];
        o0.z = acc[i][2] + bb[2]; o0.w = acc[i][3] + bb[3];
        o1.x = acc[i][4] + bb[4]; o1.y = acc[i][5] + bb[5];
        o1.z = acc[i][6] + bb[6]; o1.w = acc[i][7] + bb[7];
        *(float4*)&g_Z[m * G4 + n0 + tx * 8]     = o0;
        *(float4*)&g_Z[m * G4 + n0 + tx * 8 + 4] = o1;
    }
}

// ---------------- prep: seed h_{-1} = h0[layer] into buffer 1, tag = base ----
__global__ void k_prep(const float* __restrict__ h0l, unsigned base) {
    const int i = threadIdx.x + blockIdx.x * blockDim.x;
    if (i < HD) g_hp[1][i] = pack_ht(h0l[i], base);
}

// ---------------- recurrent persistent kernel --------------------------------
// 128 CTAs x 256 threads. CTA b owns units [8b, 8b+8); warp w -> unit u = 8b+w,
// gate rows {u, 1024+u, 2048+u, 3072+u}. Weights in registers as f32x2 pairs.
// Sync: h published as {h, tag} via one relaxed 64-bit store (no fence, no flag).
// Consumers poll their own 4 tagged words; misses back off with nanosleep so
// poll traffic stays ~15% of LTS (R3's unthrottled spin saturated it).
__global__ __launch_bounds__(256, 1) void k_rec(const float* __restrict__ Whh,  // (G4, HD)
                                                const float* __restrict__ c0l,  // (HD)
                                                float* __restrict__ Xout,       // (SEQ, HD)
                                                unsigned base) {
    __shared__ float sh[2][HD];                 // double-buffered staged h
    const int tid = threadIdx.x;
    const int w = tid >> 5, lane = tid & 31;
    const int u = blockIdx.x * 8 + w;

    unsigned sb;
    asm("{ .reg .u64 t; cvta.to.shared.u64 t, %1; cvt.u32.u64 %0, t; }"
        : "=r"(sb) : "l"((void*)sh));
    sb += (unsigned)lane * 8u;

    // packed weight pairs: lane owns k in {64j+2*lane, 64j+2*lane+1}
    unsigned long long wp[4][16];
#pragma unroll
    for (int g = 0; g < 4; g++) {
        const float* rp = Whh + (size_t)(g * HD + u) * HD + 2 * lane;
#pragma unroll
        for (int j = 0; j < 16; j++) {
            const float2 v = *(const float2*)(rp + 64 * j);
            asm("mov.b64 %0, {%1, %2};" : "=l"(wp[g][j]) : "f"(v.x), "f"(v.y));
        }
    }
    float c = c0l[u];   // only lane 0's copy is used

#pragma unroll 1
    for (int t = 0; t < SEQ; t++) {
        // per-gate z prefetch: lane g in [0,4) loads gate g's input projection
        float z = 0.f;
        if (lane < 4) z = g_Z[(size_t)t * G4 + (size_t)lane * HD + u];

        // poll own 4 tagged words (data + validity in one access), throttled
        const unsigned want = base + (unsigned)t;
        {
            const unsigned long long* p = &g_hp[(t + 1) & 1][tid * 4];
            unsigned long long v0, v1, v2, v3;
            int miss = 0;
            for (;;) {
                ld_vol2(p, v0, v1);
                ld_vol2(p + 2, v2, v3);
                const unsigned d = ((unsigned)(v0 >> 32) ^ want) | ((unsigned)(v1 >> 32) ^ want)
                                 | ((unsigned)(v2 >> 32) ^ want) | ((unsigned)(v3 >> 32) ^ want);
                if (d == 0u) break;
                if (++miss > 1) __nanosleep(miss < 4 ? (64u << miss) : 512u);
            }
            float4 hv;
            hv.x = __uint_as_float((unsigned)v0);
            hv.y = __uint_as_float((unsigned)v1);
            hv.z = __uint_as_float((unsigned)v2);
            hv.w = __uint_as_float((unsigned)v3);
            *(float4*)&sh[t & 1][tid * 4] = hv;
        }
        __syncthreads();

        // packed dot: 64 x fma.rn.f32x2 + 16 x LDS.64
        const unsigned sbase = sb + (unsigned)((t & 1) << 12);
        unsigned long long a0 = 0ull, a1 = 0ull, a2 = 0ull, a3 = 0ull;
#pragma unroll
        for (int j = 0; j < 16; j++) {
            unsigned long long hp;
            asm volatile("ld.shared.b64 %0, [%1];" : "=l"(hp) : "r"(sbase + (unsigned)(j * 256)));
            asm("fma.rn.f32x2 %0, %1, %2, %0;" : "+l"(a0) : "l"(wp[0][j]), "l"(hp));
            asm("fma.rn.f32x2 %0, %1, %2, %0;" : "+l"(a1) : "l"(wp[1][j]), "l"(hp));
            asm("fma.rn.f32x2 %0, %1, %2, %0;" : "+l"(a2) : "l"(wp[2][j]), "l"(hp));
            asm("fma.rn.f32x2 %0, %1, %2, %0;" : "+l"(a3) : "l"(wp[3][j]), "l"(hp));
        }
        float s0, s1, s2, s3;
        {
            float x, y;
            asm("mov.b64 {%0,%1}, %2;" : "=f"(x), "=f"(y) : "l"(a0)); s0 = x + y;
            asm("mov.b64 {%0,%1}, %2;" : "=f"(x), "=f"(y) : "l"(a1)); s1 = x + y;
            asm("mov.b64 {%0,%1}, %2;" : "=f"(x), "=f"(y) : "l"(a2)); s2 = x + y;
            asm("mov.b64 {%0,%1}, %2;" : "=f"(x), "=f"(y) : "l"(a3)); s3 = x + y;
        }
#pragma unroll
        for (int off = 16; off; off >>= 1) {
            s0 += __shfl_xor_sync(0xffffffffu, s0, off);
            s1 += __shfl_xor_sync(0xffffffffu, s1, off);
            s2 += __shfl_xor_sync(0xffffffffu, s2, off);
            s3 += __shfl_xor_sync(0xffffffffu, s3, off);
        }
        // spread the 4 activations across lanes 0-3 (parallel MUFU chains)
        const float sg  = (lane == 0) ? s0 : (lane == 1) ? s1 : (lane == 2) ? s2 : s3;
        const float act = (lane == 2) ? tanh_fast(sg + z) : sigmf(sg + z);
        const float ig = __shfl_sync(0xffffffffu, act, 0);
        const float fg = __shfl_sync(0xffffffffu, act, 1);
        const float gg = __shfl_sync(0xffffffffu, act, 2);
        const float og = __shfl_sync(0xffffffffu, act, 3);
        if (lane == 0) {
            c = fg * c + ig * gg;
            const float h = og * tanh_fast(c);
            st_rlx64(&g_hp[t & 1][u], pack_ht(h, want + 1u));   // publish: data+tag, one word
            Xout[(size_t)t * HD + u] = h;                        // off the critical path
        }
        // no trailing barrier: double-buffered sh + the single barrier above
        // order buffer reuse two steps apart.
    }
}

// ---------------- final: tanh(leaky_relu(X) @ w2^T + b2) ---------------------
__global__ __launch_bounds__(256) void k_final(const float* __restrict__ Xin,
                                               const float* __restrict__ w2,   // (NIN, HD)
                                               const float* __restrict__ b2,
                                               float* __restrict__ y) {
    __shared__ float xs[64][65];
    __shared__ float ws[64][65];
    const int t0 = blockIdx.x * 64;
    const int tid = threadIdx.x;
    const int o = tid & 63, tq = tid >> 6;

    float acc[16];
#pragma unroll
    for (int i = 0; i < 16; i++) acc[i] = 0.0f;

    for (int k0 = 0; k0 < HD; k0 += 64) {
        __syncthreads();
        for (int i = tid; i < 64 * 64; i += 256) {
            const int r = i >> 6, cc = i & 63;
            float v = Xin[(size_t)(t0 + r) * HD + k0 + cc];
            xs[r][cc] = (v >= 0.0f) ? v : 0.01f * v;
            ws[r][cc] = w2[(size_t)r * HD + k0 + cc];
        }
        __syncthreads();
#pragma unroll 16
        for (int k = 0; k < 64; k++) {
            const float wv = ws[o][k];
#pragma unroll
            for (int i = 0; i < 16; i++) acc[i] = fmaf(xs[tq * 16 + i][k], wv, acc[i]);
        }
    }
    const float bb = b2[o];
#pragma unroll
    for (int i = 0; i < 16; i++)
        y[(size_t)(t0 + tq * 16 + i) * NIN + o] = tanh_fast(acc[i] + bb);
}

// ---------------- host launcher ----------------------------------------------
extern "C" void kernel_launch(void* const* d_in, const int* in_sizes, int n_in,
                              void* d_out, int out_size) {
    const float* data_in = (const float*)d_in[0];
    const float* w1      = (const float*)d_in[1];
    const float* b1      = (const float*)d_in[2];
    const float* W_ih    = (const float*)d_in[3];
    const float* W_hh    = (const float*)d_in[4];
    const float* b_ih    = (const float*)d_in[5];
    const float* b_hh    = (const float*)d_in[6];
    const float* w2      = (const float*)d_in[7];
    const float* b2      = (const float*)d_in[8];
    const float* h0      = (const float*)d_in[9];
    const float* c0      = (const float*)d_in[10];
    float* out = (float*)d_out;

    static float* dA = nullptr;
    static float* dB = nullptr;
    if (!dA) {   // host-side symbol query, not an allocation
        cudaGetSymbolAddress((void**)&dA, g_bufA);
        cudaGetSymbolAddress((void**)&dB, g_bufB);
    }
    float* bufs[2] = { dA, dB };

    k_init<<<8, 256>>>();   // zero tags -> graph-replay safe
    k_first<<<dim3(SEQ / 64, HD / 64), 256>>>(data_in, w1, b1, dA);

    for (int l = 0; l < NLAYER; l++) {
        const float* Xin = bufs[l & 1];
        float* Xout = bufs[(l & 1) ^ 1];
        const unsigned base = (unsigned)(l * (SEQ + 2) + 1);   // disjoint, >0 tag ranges
        k_gemm<<<dim3(G4 / 128, SEQ / 128), 256>>>(Xin,
                                                   W_ih + (size_t)l * G4 * HD,
                                                   b_ih + (size_t)l * G4,
                                                   b_hh + (size_t)l * G4);
        k_prep<<<4, 256>>>(h0 + (size_t)l * HD, base);
        k_rec<<<NCTA, 256>>>(W_hh + (size_t)l * G4 * HD,
                             c0 + (size_t)l * HD,
                             Xout,
                             base);
    }
    k_final<<<SEQ / 64, 256>>>(bufs[NLAYER & 1], w2, b2, out);
}

// round 5
// speedup vs baseline: 1.7064x; 1.5814x over previous
#include <cuda_runtime.h>

#define SEQ   8192
#define HD    1024
#define G4    4096
#define NIN   64
#define NLAYER 5
#define NCTA  128

// ---------------- scratch (device globals; no allocation allowed) ------------
__device__ float    g_bufA[(size_t)SEQ * HD];   // 32 MB activation ping
__device__ float    g_bufB[(size_t)SEQ * HD];   // 32 MB activation pong
__device__ float    g_Z[(size_t)SEQ * G4];      // 128 MB input-projection buffer
__device__ float    g_h[2 * HD];                // double-buffered hidden state
__device__ unsigned g_flags[NCTA];              // per-CTA monotonic step flags

// ---------------- math helpers ----------------------------------------------
__device__ __forceinline__ float sigmf(float x) { return 1.0f / (1.0f + __expf(-x)); }
__device__ __forceinline__ float tanh_fast(float x) { return 1.0f - 2.0f / (__expf(2.0f * x) + 1.0f); }

__device__ __forceinline__ unsigned ld_acq(const unsigned* p) {
    unsigned v;
    asm volatile("ld.acquire.gpu.global.b32 %0, [%1];" : "=r"(v) : "l"(p) : "memory");
    return v;
}
__device__ __forceinline__ void st_rel(unsigned* p, unsigned v) {
    asm volatile("st.release.gpu.global.b32 [%0], %1;" :: "l"(p), "r"(v) : "memory");
}
__device__ __forceinline__ void st_rlx_f(float* p, float v) {
    asm volatile("st.relaxed.gpu.global.b32 [%0], %1;" :: "l"(p), "f"(v) : "memory");
}

// ---------------- init / diagnostics -----------------------------------------
__global__ void k_init() { g_flags[threadIdx.x] = 0u; }
__global__ void k_nop() {}

// ---------------- first layer: leaky_relu(x @ w1^T + b1) ---------------------
__global__ __launch_bounds__(256) void k_first(const float* __restrict__ x,
                                               const float* __restrict__ w1,
                                               const float* __restrict__ b1,
                                               float* __restrict__ out) {
    __shared__ float xs[64][NIN];
    __shared__ float ws[64][NIN + 1];
    const int t0 = blockIdx.x * 64;
    const int h0 = blockIdx.y * 64;
    const int tid = threadIdx.x;

    for (int i = tid; i < 64 * NIN; i += 256)
        xs[i >> 6][i & 63] = x[(size_t)(t0 + (i >> 6)) * NIN + (i & 63)];
    for (int i = tid; i < 64 * NIN; i += 256)
        ws[i >> 6][i & 63] = w1[(size_t)(h0 + (i >> 6)) * NIN + (i & 63)];
    __syncthreads();

    const int h = tid & 63, tq = tid >> 6;
    float acc[16];
#pragma unroll
    for (int i = 0; i < 16; i++) acc[i] = 0.0f;

#pragma unroll 16
    for (int k = 0; k < NIN; k++) {
        const float wv = ws[h][k];
#pragma unroll
        for (int i = 0; i < 16; i++) acc[i] = fmaf(xs[tq * 16 + i][k], wv, acc[i]);
    }
    const float bb = b1[h0 + h];
#pragma unroll
    for (int i = 0; i < 16; i++) {
        float v = acc[i] + bb;
        v = (v >= 0.0f) ? v : 0.01f * v;
        out[(size_t)(t0 + tq * 16 + i) * HD + h0 + h] = v;
    }
}

// ---------------- input-projection GEMM: Z = X @ Wih^T + (b_ih + b_hh) -------
// 128x128 tile, KT=16, double-buffered SMEM (1 bar/iter), conflict-free LDS
// fragments (tx*4 / tx*4+64 split). 256 threads, 8x8 accumulators.
__global__ __launch_bounds__(256, 2) void k_gemm(const float* __restrict__ A,   // (SEQ, HD)
                                                 const float* __restrict__ W,   // (G4, HD)
                                                 const float* __restrict__ bi,
                                                 const float* __restrict__ bh) {
    __shared__ float As[2][16][128];
    __shared__ float Bs[2][16][128];
    const int tid = threadIdx.x;
    const int tx = tid & 15, ty = tid >> 4;
    const int m0 = blockIdx.y * 128, n0 = blockIdx.x * 128;
    const int row = tid & 127, cq = tid >> 7;        // cq in {0,1}: k-halves
    const int kb = cq * 8;

    const float* Ap = A + (size_t)(m0 + row) * HD + kb;
    const float* Wp = W + (size_t)(n0 + row) * HD + kb;

    float4 a0 = *(const float4*)(Ap);
    float4 a1 = *(const float4*)(Ap + 4);
    float4 b0 = *(const float4*)(Wp);
    float4 b1 = *(const float4*)(Wp + 4);

    As[0][kb + 0][row] = a0.x; As[0][kb + 1][row] = a0.y;
    As[0][kb + 2][row] = a0.z; As[0][kb + 3][row] = a0.w;
    As[0][kb + 4][row] = a1.x; As[0][kb + 5][row] = a1.y;
    As[0][kb + 6][row] = a1.z; As[0][kb + 7][row] = a1.w;
    Bs[0][kb + 0][row] = b0.x; Bs[0][kb + 1][row] = b0.y;
    Bs[0][kb + 2][row] = b0.z; Bs[0][kb + 3][row] = b0.w;
    Bs[0][kb + 4][row] = b1.x; Bs[0][kb + 5][row] = b1.y;
    Bs[0][kb + 6][row] = b1.z; Bs[0][kb + 7][row] = b1.w;
    __syncthreads();

    float acc[8][8];
#pragma unroll
    for (int i = 0; i < 8; i++)
#pragma unroll
        for (int j = 0; j < 8; j++) acc[i][j] = 0.0f;

    for (int kt = 0; kt < HD / 16; ++kt) {
        const int p = kt & 1;
        if (kt < HD / 16 - 1) {                       // prefetch next k-tile
            const float* Ap2 = Ap + (kt + 1) * 16;
            const float* Wp2 = Wp + (kt + 1) * 16;
            a0 = *(const float4*)(Ap2);
            a1 = *(const float4*)(Ap2 + 4);
            b0 = *(const float4*)(Wp2);
            b1 = *(const float4*)(Wp2 + 4);
        }
#pragma unroll
        for (int kk = 0; kk < 16; kk++) {
            float ar[8], br[8];
            *(float4*)(ar)     = *(const float4*)&As[p][kk][ty * 4];
            *(float4*)(ar + 4) = *(const float4*)&As[p][kk][ty * 4 + 64];
            *(float4*)(br)     = *(const float4*)&Bs[p][kk][tx * 4];
            *(float4*)(br + 4) = *(const float4*)&Bs[p][kk][tx * 4 + 64];
#pragma unroll
            for (int i = 0; i < 8; i++)
#pragma unroll
                for (int j = 0; j < 8; j++) acc[i][j] = fmaf(ar[i], br[j], acc[i][j]);
        }
        if (kt < HD / 16 - 1) {
            const int q = p ^ 1;
            As[q][kb + 0][row] = a0.x; As[q][kb + 1][row] = a0.y;
            As[q][kb + 2][row] = a0.z; As[q][kb + 3][row] = a0.w;
            As[q][kb + 4][row] = a1.x; As[q][kb + 5][row] = a1.y;
            As[q][kb + 6][row] = a1.z; As[q][kb + 7][row] = a1.w;
            Bs[q][kb + 0][row] = b0.x; Bs[q][kb + 1][row] = b0.y;
            Bs[q][kb + 2][row] = b0.z; Bs[q][kb + 3][row] = b0.w;
            Bs[q][kb + 4][row] = b1.x; Bs[q][kb + 5][row] = b1.y;
            Bs[q][kb + 6][row] = b1.z; Bs[q][kb + 7][row] = b1.w;
            __syncthreads();
        }
    }

    float bb[8];
#pragma unroll
    for (int j = 0; j < 8; j++) {
        const int cn = n0 + ((j < 4) ? (tx * 4 + j) : (64 + tx * 4 + j - 4));
        bb[j] = bi[cn] + bh[cn];
    }
#pragma unroll
    for (int i = 0; i < 8; i++) {
        const size_t m = (size_t)(m0 + ((i < 4) ? (ty * 4 + i) : (64 + ty * 4 + i - 4)));
        float4 o0, o1;
        o0.x = acc[i][0] + bb[0]; o0.y = acc[i][1] + bb[1];
        o0.z = acc[i][2] + bb[2]; o0.w = acc[i][3] + bb[3];
        o1.x = acc[i][4] + bb[4]; o1.y = acc[i][5] + bb[5];
        o1.z = acc[i][6] + bb[6]; o1.w = acc[i][7] + bb[7];
        *(float4*)&g_Z[m * G4 + n0 + tx * 4]      = o0;
        *(float4*)&g_Z[m * G4 + n0 + 64 + tx * 4] = o1;
    }
}

// ---------------- prep: seed h_{-1} = h0[layer] into buffer 1 ----------------
__global__ void k_prep(const float* __restrict__ h0l) {
    const int i = threadIdx.x + blockIdx.x * blockDim.x;
    if (i < HD) g_h[HD + i] = h0l[i];   // t=0 reads buf[1]
}

// ---------------- recurrent persistent kernel --------------------------------
// 128 CTAs x 256 threads. CTA b owns units [8b, 8b+8); warp w -> unit u = 8b+w,
// gate rows {u, 1024+u, 2048+u, 3072+u}. Weights in registers as f32x2 pairs.
// Sync (fence-free message passing): lane0 h -> st.relaxed.gpu; __syncthreads;
// tid0 flag -> st.release.gpu. Consumers ld.acquire the per-CTA flag (4B poll),
// then one 16B h load. (R3/R4 taught: poll bytes must stay tiny.)
__global__ __launch_bounds__(256, 1) void k_rec(const float* __restrict__ Whh,  // (G4, HD)
                                                const float* __restrict__ c0l,  // (HD)
                                                float* __restrict__ Xout,       // (SEQ, HD)
                                                unsigned base) {
    __shared__ float sh[2][HD];                 // double-buffered staged h
    const int tid = threadIdx.x;
    const int w = tid >> 5, lane = tid & 31;
    const int u = blockIdx.x * 8 + w;

    unsigned sb;
    asm("{ .reg .u64 t; cvta.to.shared.u64 t, %1; cvt.u32.u64 %0, t; }"
        : "=r"(sb) : "l"((void*)sh));
    sb += (unsigned)lane * 8u;

    // packed weight pairs: lane owns k in {64j+2*lane, 64j+2*lane+1}
    unsigned long long wp[4][16];
#pragma unroll
    for (int g = 0; g < 4; g++) {
        const float* rp = Whh + (size_t)(g * HD + u) * HD + 2 * lane;
#pragma unroll
        for (int j = 0; j < 16; j++) {
            const float2 v = *(const float2*)(rp + 64 * j);
            asm("mov.b64 %0, {%1, %2};" : "=l"(wp[g][j]) : "f"(v.x), "f"(v.y));
        }
    }
    float c = c0l[u];   // only lane 0's copy is used

#pragma unroll 1
    for (int t = 0; t < SEQ; t++) {
        // per-gate z prefetch: lane g in [0,4) loads gate g's input projection
        float z = 0.f;
        if (lane < 4) z = g_Z[(size_t)t * G4 + (size_t)lane * HD + u];

        // wait only for the CTA producing THIS thread's float4 slice of h
        const unsigned target = base + (unsigned)t;
        {
            const unsigned* fp = &g_flags[tid >> 1];
            while (ld_acq(fp) < target) {}
            const float4 v = __ldcg((const float4*)(g_h + ((t + 1) & 1) * HD) + tid);
            *(float4*)&sh[t & 1][tid * 4] = v;
        }
        __syncthreads();

        // packed dot: 64 x fma.rn.f32x2 + 16 x LDS.64
        const unsigned sbase = sb + (unsigned)((t & 1) << 12);
        unsigned long long a0 = 0ull, a1 = 0ull, a2 = 0ull, a3 = 0ull;
#pragma unroll
        for (int j = 0; j < 16; j++) {
            unsigned long long hp;
            asm volatile("ld.shared.b64 %0, [%1];" : "=l"(hp) : "r"(sbase + (unsigned)(j * 256)));
            asm("fma.rn.f32x2 %0, %1, %2, %0;" : "+l"(a0) : "l"(wp[0][j]), "l"(hp));
            asm("fma.rn.f32x2 %0, %1, %2, %0;" : "+l"(a1) : "l"(wp[1][j]), "l"(hp));
            asm("fma.rn.f32x2 %0, %1, %2, %0;" : "+l"(a2) : "l"(wp[2][j]), "l"(hp));
            asm("fma.rn.f32x2 %0, %1, %2, %0;" : "+l"(a3) : "l"(wp[3][j]), "l"(hp));
        }
        float s0, s1, s2, s3;
        {
            float x, y;
            asm("mov.b64 {%0,%1}, %2;" : "=f"(x), "=f"(y) : "l"(a0)); s0 = x + y;
            asm("mov.b64 {%0,%1}, %2;" : "=f"(x), "=f"(y) : "l"(a1)); s1 = x + y;
            asm("mov.b64 {%0,%1}, %2;" : "=f"(x), "=f"(y) : "l"(a2)); s2 = x + y;
            asm("mov.b64 {%0,%1}, %2;" : "=f"(x), "=f"(y) : "l"(a3)); s3 = x + y;
        }
#pragma unroll
        for (int off = 16; off; off >>= 1) {
            s0 += __shfl_xor_sync(0xffffffffu, s0, off);
            s1 += __shfl_xor_sync(0xffffffffu, s1, off);
            s2 += __shfl_xor_sync(0xffffffffu, s2, off);
            s3 += __shfl_xor_sync(0xffffffffu, s3, off);
        }
        // 4 parallel activation chains on lanes 0-3
        const float sg  = (lane == 0) ? s0 : (lane == 1) ? s1 : (lane == 2) ? s2 : s3;
        const float act = (lane == 2) ? tanh_fast(sg + z) : sigmf(sg + z);
        const float ig = __shfl_sync(0xffffffffu, act, 0);
        const float fg = __shfl_sync(0xffffffffu, act, 1);
        const float gg = __shfl_sync(0xffffffffu, act, 2);
        const float og = __shfl_sync(0xffffffffu, act, 3);
        float h = 0.f;
        if (lane == 0) {
            c = fg * c + ig * gg;
            h = og * tanh_fast(c);
            st_rlx_f(&g_h[(t & 1) * HD + u], h);    // strong store (gpu scope)
        }
        __syncthreads();                            // all h stores happen-before flag
        if (tid == 0)
            st_rel(&g_flags[blockIdx.x], target + 1u);   // release: publishes h
        if (lane == 0)
            Xout[(size_t)t * HD + u] = h;           // off the critical path
    }
}

// ---------------- final: tanh(leaky_relu(X) @ w2^T + b2) ---------------------
__global__ __launch_bounds__(256) void k_final(const float* __restrict__ Xin,
                                               const float* __restrict__ w2,   // (NIN, HD)
                                               const float* __restrict__ b2,
                                               float* __restrict__ y) {
    __shared__ float xs[64][65];
    __shared__ float ws[64][65];
    const int t0 = blockIdx.x * 64;
    const int tid = threadIdx.x;
    const int o = tid & 63, tq = tid >> 6;

    float acc[16];
#pragma unroll
    for (int i = 0; i < 16; i++) acc[i] = 0.0f;

    for (int k0 = 0; k0 < HD; k0 += 64) {
        __syncthreads();
        for (int i = tid; i < 64 * 64; i += 256) {
            const int r = i >> 6, cc = i & 63;
            float v = Xin[(size_t)(t0 + r) * HD + k0 + cc];
            xs[r][cc] = (v >= 0.0f) ? v : 0.01f * v;
            ws[r][cc] = w2[(size_t)r * HD + k0 + cc];
        }
        __syncthreads();
#pragma unroll 16
        for (int k = 0; k < 64; k++) {
            const float wv = ws[o][k];
#pragma unroll
            for (int i = 0; i < 16; i++) acc[i] = fmaf(xs[tq * 16 + i][k], wv, acc[i]);
        }
    }
    const float bb = b2[o];
#pragma unroll
    for (int i = 0; i < 16; i++)
        y[(size_t)(t0 + tq * 16 + i) * NIN + o] = tanh_fast(acc[i] + bb);
}

// ---------------- host launcher ----------------------------------------------
extern "C" void kernel_launch(void* const* d_in, const int* in_sizes, int n_in,
                              void* d_out, int out_size) {
    const float* data_in = (const float*)d_in[0];
    const float* w1      = (const float*)d_in[1];
    const float* b1      = (const float*)d_in[2];
    const float* W_ih    = (const float*)d_in[3];
    const float* W_hh    = (const float*)d_in[4];
    const float* b_ih    = (const float*)d_in[5];
    const float* b_hh    = (const float*)d_in[6];
    const float* w2      = (const float*)d_in[7];
    const float* b2      = (const float*)d_in[8];
    const float* h0      = (const float*)d_in[9];
    const float* c0      = (const float*)d_in[10];
    float* out = (float*)d_out;

    static float* dA = nullptr;
    static float* dB = nullptr;
    if (!dA) {   // host-side symbol query, not an allocation
        cudaGetSymbolAddress((void**)&dA, g_bufA);
        cudaGetSymbolAddress((void**)&dB, g_bufB);
    }
    float* bufs[2] = { dA, dB };

    k_init<<<1, NCTA>>>();                                       // launch 1
    k_first<<<dim3(SEQ / 64, HD / 64), 256>>>(data_in, w1, b1, dA);  // 2

    for (int l = 0; l < NLAYER; l++) {
        const float* Xin = bufs[l & 1];
        float* Xout = bufs[(l & 1) ^ 1];
        k_gemm<<<dim3(G4 / 128, SEQ / 128), 256>>>(Xin,          // 3, 8, 11, ...
                                                   W_ih + (size_t)l * G4 * HD,
                                                   b_ih + (size_t)l * G4,
                                                   b_hh + (size_t)l * G4);
        k_prep<<<4, 256>>>(h0 + (size_t)l * HD);                 // 4
        if (l == 0) { k_nop<<<1, 32>>>(); k_nop<<<1, 32>>>(); }  // 5, 6: align ncu slot 7 -> k_rec
        k_rec<<<NCTA, 256>>>(W_hh + (size_t)l * G4 * HD,         // 7 (profiled)
                             c0 + (size_t)l * HD,
                             Xout,
                             (unsigned)(l * SEQ));
    }
    k_final<<<SEQ / 64, 256>>>(bufs[NLAYER & 1], w2, b2, out);
}

// round 6
// speedup vs baseline: 1.7353x; 1.0170x over previous
#include <cuda_runtime.h>

#define SEQ   8192
#define HD    1024
#define G4    4096
#define NIN   64
#define NLAYER 5
#define NCTA  128

// ---------------- scratch (device globals; no allocation allowed) ------------
__device__ float    g_bufA[(size_t)SEQ * HD];   // 32 MB activation ping
__device__ float    g_bufB[(size_t)SEQ * HD];   // 32 MB activation pong
__device__ float    g_Z[(size_t)SEQ * G4];      // 128 MB input-projection buffer
__device__ float    g_h[2 * HD];                // double-buffered hidden state
__device__ unsigned g_flags[NCTA];              // per-CTA monotonic step flags

// ---------------- math helpers ----------------------------------------------
__device__ __forceinline__ float sigmf(float x) { return 1.0f / (1.0f + __expf(-x)); }
__device__ __forceinline__ float tanh_fast(float x) { return 1.0f - 2.0f / (__expf(2.0f * x) + 1.0f); }

__device__ __forceinline__ unsigned ld_acq(const unsigned* p) {
    unsigned v;
    asm volatile("ld.acquire.gpu.global.b32 %0, [%1];" : "=r"(v) : "l"(p) : "memory");
    return v;
}
__device__ __forceinline__ void st_rel(unsigned* p, unsigned v) {
    asm volatile("st.release.gpu.global.b32 [%0], %1;" :: "l"(p), "r"(v) : "memory");
}
__device__ __forceinline__ void st_rlx_f(float* p, float v) {
    asm volatile("st.relaxed.gpu.global.b32 [%0], %1;" :: "l"(p), "f"(v) : "memory");
}

// ---------------- init: flags = 0, seed layer-0 h_{-1} -----------------------
__global__ void k_init(const float* __restrict__ h0l) {
    const int i = threadIdx.x + blockIdx.x * blockDim.x;   // 0..1023
    if (i < NCTA) g_flags[i] = 0u;
    g_h[HD + i] = h0l[i];    // t=0 reads buf[1]
}

// ---------------- prep (layers >= 1): seed h_{-1} = h0[layer] ----------------
__global__ void k_prep(const float* __restrict__ h0l) {
    const int i = threadIdx.x + blockIdx.x * blockDim.x;
    if (i < HD) g_h[HD + i] = h0l[i];
}

// ---------------- first layer: leaky_relu(x @ w1^T + b1) ---------------------
__global__ __launch_bounds__(256) void k_first(const float* __restrict__ x,
                                               const float* __restrict__ w1,
                                               const float* __restrict__ b1,
                                               float* __restrict__ out) {
    __shared__ float xs[64][NIN];
    __shared__ float ws[64][NIN + 1];
    const int t0 = blockIdx.x * 64;
    const int h0 = blockIdx.y * 64;
    const int tid = threadIdx.x;

    for (int i = tid; i < 64 * NIN; i += 256)
        xs[i >> 6][i & 63] = x[(size_t)(t0 + (i >> 6)) * NIN + (i & 63)];
    for (int i = tid; i < 64 * NIN; i += 256)
        ws[i >> 6][i & 63] = w1[(size_t)(h0 + (i >> 6)) * NIN + (i & 63)];
    __syncthreads();

    const int h = tid & 63, tq = tid >> 6;
    float acc[16];
#pragma unroll
    for (int i = 0; i < 16; i++) acc[i] = 0.0f;

#pragma unroll 16
    for (int k = 0; k < NIN; k++) {
        const float wv = ws[h][k];
#pragma unroll
        for (int i = 0; i < 16; i++) acc[i] = fmaf(xs[tq * 16 + i][k], wv, acc[i]);
    }
    const float bb = b1[h0 + h];
#pragma unroll
    for (int i = 0; i < 16; i++) {
        float v = acc[i] + bb;
        v = (v >= 0.0f) ? v : 0.01f * v;
        out[(size_t)(t0 + tq * 16 + i) * HD + h0 + h] = v;
    }
}

// ---------------- input-projection GEMM (R2 version, known-good) -------------
// 128x128x8 SGEMM, 256 threads, 8x8 accumulators, register prefetch.
__global__ __launch_bounds__(256, 2) void k_gemm(const float* __restrict__ A,   // (SEQ, HD)
                                                 const float* __restrict__ W,   // (G4, HD)
                                                 const float* __restrict__ bi,
                                                 const float* __restrict__ bh) {
    __shared__ float As[8][128];
    __shared__ float Bs[8][128];
    const int tid = threadIdx.x;
    const int tx = tid & 15, ty = tid >> 4;
    const int m0 = blockIdx.y * 128, n0 = blockIdx.x * 128;
    const int lr = tid >> 1, lk = (tid & 1) * 4;

    const float* Ap = A + (size_t)(m0 + lr) * HD + lk;
    const float* Wp = W + (size_t)(n0 + lr) * HD + lk;

    float acc[8][8];
#pragma unroll
    for (int i = 0; i < 8; i++)
#pragma unroll
        for (int j = 0; j < 8; j++) acc[i][j] = 0.0f;

    float4 av = *(const float4*)(Ap);
    float4 bv = *(const float4*)(Wp);

    for (int k0 = 0; k0 < HD; k0 += 8) {
        __syncthreads();
        As[lk + 0][lr] = av.x; As[lk + 1][lr] = av.y; As[lk + 2][lr] = av.z; As[lk + 3][lr] = av.w;
        Bs[lk + 0][lr] = bv.x; Bs[lk + 1][lr] = bv.y; Bs[lk + 2][lr] = bv.z; Bs[lk + 3][lr] = bv.w;
        __syncthreads();
        if (k0 + 8 < HD) {
            av = *(const float4*)(Ap + k0 + 8);
            bv = *(const float4*)(Wp + k0 + 8);
        }
#pragma unroll
        for (int kk = 0; kk < 8; kk++) {
            float ar[8], br[8];
            *(float4*)(ar)     = *(const float4*)&As[kk][ty * 8];
            *(float4*)(ar + 4) = *(const float4*)&As[kk][ty * 8 + 4];
            *(float4*)(br)     = *(const float4*)&Bs[kk][tx * 8];
            *(float4*)(br + 4) = *(const float4*)&Bs[kk][tx * 8 + 4];
#pragma unroll
            for (int i = 0; i < 8; i++)
#pragma unroll
                for (int j = 0; j < 8; j++) acc[i][j] = fmaf(ar[i], br[j], acc[i][j]);
        }
    }
    float bb[8];
#pragma unroll
    for (int j = 0; j < 8; j++) bb[j] = bi[n0 + tx * 8 + j] + bh[n0 + tx * 8 + j];
#pragma unroll
    for (int i = 0; i < 8; i++) {
        const size_t m = (size_t)(m0 + ty * 8 + i);
        float4 o0, o1;
        o0.x = acc[i][0] + bb[0]; o0.y = acc[i][1] + bb[1];
        o0.z = acc[i][2] + bb[2]; o0.w = acc[i][3] + bb[3];
        o1.x = acc[i][4] + bb[4]; o1.y = acc[i][5] + bb[5];
        o1.z = acc[i][6] + bb[6]; o1.w = acc[i][7] + bb[7];
        *(float4*)&g_Z[m * G4 + n0 + tx * 8]     = o0;
        *(float4*)&g_Z[m * G4 + n0 + tx * 8 + 4] = o1;
    }
}

// ---------------- recurrent persistent kernel --------------------------------
// 128 CTAs x 256 threads. CTA b owns units [8b, 8b+8); warp w -> unit u = 8b+w,
// gate rows {u, 1024+u, 2048+u, 3072+u}. Weights in registers as f32x2 pairs.
// Sync: lane0 h -> st.relaxed.gpu; __syncthreads; tid0 flag -> st.release.gpu.
// Consumers ld.acquire their slice producer's flag (4B poll), then 16B h load.
__global__ __launch_bounds__(256, 1) void k_rec(const float* __restrict__ Whh,  // (G4, HD)
                                                const float* __restrict__ c0l,  // (HD)
                                                float* __restrict__ Xout,       // (SEQ, HD)
                                                unsigned base) {
    __shared__ float sh[2][HD];                 // double-buffered staged h
    const int tid = threadIdx.x;
    const int w = tid >> 5, lane = tid & 31;
    const int u = blockIdx.x * 8 + w;

    unsigned sb;
    asm("{ .reg .u64 t; cvta.to.shared.u64 t, %1; cvt.u32.u64 %0, t; }"
        : "=r"(sb) : "l"((void*)sh));
    sb += (unsigned)lane * 8u;

    // packed weight pairs: lane owns k in {64j+2*lane, 64j+2*lane+1}
    unsigned long long wp[4][16];
#pragma unroll
    for (int g = 0; g < 4; g++) {
        const float* rp = Whh + (size_t)(g * HD + u) * HD + 2 * lane;
#pragma unroll
        for (int j = 0; j < 16; j++) {
            const float2 v = *(const float2*)(rp + 64 * j);
            asm("mov.b64 %0, {%1, %2};" : "=l"(wp[g][j]) : "f"(v.x), "f"(v.y));
        }
    }
    float c = c0l[u];   // only lane 0's copy is used

#pragma unroll 1
    for (int t = 0; t < SEQ; t++) {
        // per-gate z prefetch: lane g in [0,4) loads gate g's input projection
        float z = 0.f;
        if (lane < 4) z = __ldcg(g_Z + (size_t)t * G4 + (size_t)lane * HD + u);

        // wait only for the CTA producing THIS thread's float4 slice of h
        const unsigned target = base + (unsigned)t;
        {
            const unsigned* fp = &g_flags[tid >> 1];
            while (ld_acq(fp) < target) {}
            const float4 v = __ldcg((const float4*)(g_h + ((t + 1) & 1) * HD) + tid);
            *(float4*)&sh[t & 1][tid * 4] = v;
        }
        __syncthreads();

        // packed dot: 64 x fma.rn.f32x2 + 16 x LDS.64
        const unsigned sbase = sb + (unsigned)((t & 1) << 12);
        unsigned long long a0 = 0ull, a1 = 0ull, a2 = 0ull, a3 = 0ull;
#pragma unroll
        for (int j = 0; j < 16; j++) {
            unsigned long long hp;
            asm volatile("ld.shared.b64 %0, [%1];" : "=l"(hp) : "r"(sbase + (unsigned)(j * 256)));
            asm("fma.rn.f32x2 %0, %1, %2, %0;" : "+l"(a0) : "l"(wp[0][j]), "l"(hp));
            asm("fma.rn.f32x2 %0, %1, %2, %0;" : "+l"(a1) : "l"(wp[1][j]), "l"(hp));
            asm("fma.rn.f32x2 %0, %1, %2, %0;" : "+l"(a2) : "l"(wp[2][j]), "l"(hp));
            asm("fma.rn.f32x2 %0, %1, %2, %0;" : "+l"(a3) : "l"(wp[3][j]), "l"(hp));
        }
        float s0, s1, s2, s3;
        {
            float x, y;
            asm("mov.b64 {%0,%1}, %2;" : "=f"(x), "=f"(y) : "l"(a0)); s0 = x + y;
            asm("mov.b64 {%0,%1}, %2;" : "=f"(x), "=f"(y) : "l"(a1)); s1 = x + y;
            asm("mov.b64 {%0,%1}, %2;" : "=f"(x), "=f"(y) : "l"(a2)); s2 = x + y;
            asm("mov.b64 {%0,%1}, %2;" : "=f"(x), "=f"(y) : "l"(a3)); s3 = x + y;
        }
#pragma unroll
        for (int off = 16; off; off >>= 1) {
            s0 += __shfl_xor_sync(0xffffffffu, s0, off);
            s1 += __shfl_xor_sync(0xffffffffu, s1, off);
            s2 += __shfl_xor_sync(0xffffffffu, s2, off);
            s3 += __shfl_xor_sync(0xffffffffu, s3, off);
        }
        // 4 parallel activation chains on lanes 0-3
        const float sg  = (lane == 0) ? s0 : (lane == 1) ? s1 : (lane == 2) ? s2 : s3;
        const float act = (lane == 2) ? tanh_fast(sg + z) : sigmf(sg + z);
        const float ig = __shfl_sync(0xffffffffu, act, 0);
        const float fg = __shfl_sync(0xffffffffu, act, 1);
        const float gg = __shfl_sync(0xffffffffu, act, 2);
        const float og = __shfl_sync(0xffffffffu, act, 3);
        float h = 0.f;
        if (lane == 0) {
            c = fg * c + ig * gg;
            h = og * tanh_fast(c);
            st_rlx_f(&g_h[(t & 1) * HD + u], h);    // strong store (gpu scope)
        }
        __syncthreads();                            // all h stores happen-before flag
        if (tid == 0)
            st_rel(&g_flags[blockIdx.x], target + 1u);   // release: publishes h
        if (lane == 0)
            Xout[(size_t)t * HD + u] = h;           // off the critical path
    }
}

// ---------------- final: tanh(leaky_relu(X) @ w2^T + b2) ---------------------
__global__ __launch_bounds__(256) void k_final(const float* __restrict__ Xin,
                                               const float* __restrict__ w2,   // (NIN, HD)
                                               const float* __restrict__ b2,
                                               float* __restrict__ y) {
    __shared__ float xs[64][65];
    __shared__ float ws[64][65];
    const int t0 = blockIdx.x * 64;
    const int tid = threadIdx.x;
    const int o = tid & 63, tq = tid >> 6;

    float acc[16];
#pragma unroll
    for (int i = 0; i < 16; i++) acc[i] = 0.0f;

    for (int k0 = 0; k0 < HD; k0 += 64) {
        __syncthreads();
        for (int i = tid; i < 64 * 64; i += 256) {
            const int r = i >> 6, cc = i & 63;
            float v = Xin[(size_t)(t0 + r) * HD + k0 + cc];
            xs[r][cc] = (v >= 0.0f) ? v : 0.01f * v;
            ws[r][cc] = w2[(size_t)r * HD + k0 + cc];
        }
        __syncthreads();
#pragma unroll 16
        for (int k = 0; k < 64; k++) {
            const float wv = ws[o][k];
#pragma unroll
            for (int i = 0; i < 16; i++) acc[i] = fmaf(xs[tq * 16 + i][k], wv, acc[i]);
        }
    }
    const float bb = b2[o];
#pragma unroll
    for (int i = 0; i < 16; i++)
        y[(size_t)(t0 + tq * 16 + i) * NIN + o] = tanh_fast(acc[i] + bb);
}

// ---------------- host launcher ----------------------------------------------
extern "C" void kernel_launch(void* const* d_in, const int* in_sizes, int n_in,
                              void* d_out, int out_size) {
    const float* data_in = (const float*)d_in[0];
    const float* w1      = (const float*)d_in[1];
    const float* b1      = (const float*)d_in[2];
    const float* W_ih    = (const float*)d_in[3];
    const float* W_hh    = (const float*)d_in[4];
    const float* b_ih    = (const float*)d_in[5];
    const float* b_hh    = (const float*)d_in[6];
    const float* w2      = (const float*)d_in[7];
    const float* b2      = (const float*)d_in[8];
    const float* h0      = (const float*)d_in[9];
    const float* c0      = (const float*)d_in[10];
    float* out = (float*)d_out;

    static float* dA = nullptr;
    static float* dB = nullptr;
    if (!dA) {   // host-side symbol query, not an allocation
        cudaGetSymbolAddress((void**)&dA, g_bufA);
        cudaGetSymbolAddress((void**)&dB, g_bufB);
    }
    float* bufs[2] = { dA, dB };

    k_init<<<4, 256>>>(h0);                                        // launch 1: flags + layer-0 h seed
    k_first<<<dim3(SEQ / 64, HD / 64), 256>>>(data_in, w1, b1, dA);  // launch 2

    for (int l = 0; l < NLAYER; l++) {
        const float* Xin = bufs[l & 1];
        float* Xout = bufs[(l & 1) ^ 1];
        if (l > 0)
            k_prep<<<4, 256>>>(h0 + (size_t)l * HD);   // after rec(l-1), stream-ordered
        k_gemm<<<dim3(G4 / 128, SEQ / 128), 256>>>(Xin,             // launch 3 for l=0
                                                   W_ih + (size_t)l * G4 * HD,
                                                   b_ih + (size_t)l * G4,
                                                   b_hh + (size_t)l * G4);
        k_rec<<<NCTA, 256>>>(W_hh + (size_t)l * G4 * HD,            // launch 4 for l=0 -> profiled
                             c0 + (size_t)l * HD,
                             Xout,
                             (unsigned)(l * SEQ));
    }
    k_final<<<SEQ / 64, 256>>>(bufs[NLAYER & 1], w2, b2, out);
}